// round 3
// baseline (speedup 1.0000x reference)
#include <cuda_runtime.h>
#include <cuda_fp16.h>

#define NN 50000
#define NE 1600000

// Scratch (device globals; zero-initialized at module load).
__device__ __half g_h2[NN * 128];      // fp16 projected features
__device__ float  g_s[NN * 4];         // alpha_src per node/head
__device__ float  g_d[NN * 4];         // alpha_dst per node/head
__device__ int    g_last[NN];          // last edge with src==n, else -1
__device__ int    g_cnt[NN];           // out-degree histogram
__device__ int    g_start[NN + 1];     // segment starts (exclusive scan)
__device__ int    g_pos[NN];           // placement cursors
__device__ int    g_dste[NE];          // dst indices sorted by src
__device__ float  g_expv[NN * 4];      // exp(leaky(logit)); 0 for no-edge nodes
__device__ float  g_sum[4];            // softmax denominators
__device__ float  g_inv[4];            // 0.25 / g_sum

// ---------------------------------------------------------------------------
// K1: h = x@W + b (fp32 FMA, round-1 proven layout). Epilogue: fp16 h2 store
// + fused attention dot products. No fp32 h store (nothing consumes it).
// ---------------------------------------------------------------------------
__global__ __launch_bounds__(256) void gemm_h(const float* __restrict__ x,
                                              const float* __restrict__ W,
                                              const float* __restrict__ b,
                                              const float* __restrict__ asrc,
                                              const float* __restrict__ adst,
                                              int N)
{
    __shared__ float sW[32 * 128];
    __shared__ float sx[64 * 32];

    const int tid  = threadIdx.x;
    const int tx   = tid & 31;
    const int ty   = tid >> 5;
    const int row0 = blockIdx.x * 64;

    float acc[8][4];
#pragma unroll
    for (int i = 0; i < 8; i++) { acc[i][0] = acc[i][1] = acc[i][2] = acc[i][3] = 0.f; }

    for (int kk = 0; kk < 128; kk += 32) {
        {
            int r = tid >> 5;
            int c = (tid & 31) * 4;
#pragma unroll
            for (int i = 0; i < 4; i++) {
                int k = kk + r + 8 * i;
                float4 wv = *reinterpret_cast<const float4*>(&W[k * 128 + c]);
                *reinterpret_cast<float4*>(&sW[(r + 8 * i) * 128 + c]) = wv;
            }
        }
        {
            int r = tid >> 3;
            int c = (tid & 7) * 4;
#pragma unroll
            for (int i = 0; i < 2; i++) {
                int row = row0 + r + 32 * i;
                int rr  = row < N ? row : (N - 1);
                float4 xv = *reinterpret_cast<const float4*>(&x[(size_t)rr * 128 + kk + c]);
                *reinterpret_cast<float4*>(&sx[(r + 32 * i) * 32 + c]) = xv;
            }
        }
        __syncthreads();

#pragma unroll
        for (int k = 0; k < 32; k++) {
            float4 wv = *reinterpret_cast<const float4*>(&sW[k * 128 + tx * 4]);
#pragma unroll
            for (int i = 0; i < 8; i++) {
                float xv = sx[(ty * 8 + i) * 32 + k];
                acc[i][0] += xv * wv.x;
                acc[i][1] += xv * wv.y;
                acc[i][2] += xv * wv.z;
                acc[i][3] += xv * wv.w;
            }
        }
        __syncthreads();
    }

    const float4 bv  = *reinterpret_cast<const float4*>(&b[tx * 4]);
    const float4 asv = *reinterpret_cast<const float4*>(&asrc[tx * 4]);
    const float4 adv = *reinterpret_cast<const float4*>(&adst[tx * 4]);

#pragma unroll
    for (int i = 0; i < 8; i++) {
        int row = row0 + ty * 8 + i;
        if (row < N) {
            float ox = acc[i][0] + bv.x;
            float oy = acc[i][1] + bv.y;
            float oz = acc[i][2] + bv.z;
            float ow = acc[i][3] + bv.w;

            __half2 p0 = __floats2half2_rn(ox, oy);
            __half2 p1 = __floats2half2_rn(oz, ow);
            uint2 hv;
            hv.x = *reinterpret_cast<unsigned int*>(&p0);
            hv.y = *reinterpret_cast<unsigned int*>(&p1);
            *reinterpret_cast<uint2*>(&g_h2[(size_t)row * 128 + tx * 4]) = hv;

            float ps = ox * asv.x + oy * asv.y + oz * asv.z + ow * asv.w;
            float pd = ox * adv.x + oy * adv.y + oz * adv.z + ow * adv.w;
#pragma unroll
            for (int off = 4; off > 0; off >>= 1) {
                ps += __shfl_down_sync(0xffffffffu, ps, off);
                pd += __shfl_down_sync(0xffffffffu, pd, off);
            }
            if ((tx & 7) == 0) {
                int head = tx >> 3;
                g_s[row * 4 + head] = ps;
                g_d[row * 4 + head] = pd;
            }
        }
    }
}

// ---------------------------------------------------------------------------
// K2: init per-launch state (graph replays must be deterministic).
// ---------------------------------------------------------------------------
__global__ void init_k(int N)
{
    int i = blockIdx.x * blockDim.x + threadIdx.x;
    if (i < N) { g_last[i] = -1; g_cnt[i] = 0; }
    if (i < 4) g_sum[i] = 0.f;
}

// ---------------------------------------------------------------------------
// K3: fused last[src]=max(e) + degree histogram. 4 edges/thread.
// ---------------------------------------------------------------------------
__global__ void last_cnt_k(const int* __restrict__ src, int E)
{
    int i = blockIdx.x * blockDim.x + threadIdx.x;
    int e0 = i * 4;
    if (e0 + 3 < E) {
        int4 s = *reinterpret_cast<const int4*>(&src[e0]);
        atomicMax(&g_last[s.x], e0);
        atomicMax(&g_last[s.y], e0 + 1);
        atomicMax(&g_last[s.z], e0 + 2);
        atomicMax(&g_last[s.w], e0 + 3);
        atomicAdd(&g_cnt[s.x], 1);
        atomicAdd(&g_cnt[s.y], 1);
        atomicAdd(&g_cnt[s.z], 1);
        atomicAdd(&g_cnt[s.w], 1);
    } else {
        for (int e = e0; e < E; e++) {
            int s = src[e];
            atomicMax(&g_last[s], e);
            atomicAdd(&g_cnt[s], 1);
        }
    }
}

// ---------------------------------------------------------------------------
// K4: exclusive scan of g_cnt -> g_start (and g_pos). Single block, 1024 thr.
// ---------------------------------------------------------------------------
__global__ __launch_bounds__(1024) void scan_k(int N, int E)
{
    __shared__ int tot[1024];
    const int t = threadIdx.x;
    const int chunk = (N + 1023) / 1024;
    const int beg = t * chunk;
    const int end = min(beg + chunk, N);

    int s = 0;
    for (int i = beg; i < end; i++) s += g_cnt[i];
    tot[t] = s;
    __syncthreads();

    // Hillis-Steele inclusive scan
    for (int off = 1; off < 1024; off <<= 1) {
        int u = (t >= off) ? tot[t - off] : 0;
        __syncthreads();
        tot[t] += u;
        __syncthreads();
    }

    int run = (t > 0) ? tot[t - 1] : 0;
    for (int i = beg; i < end; i++) {
        int c = g_cnt[i];
        g_start[i] = run;
        g_pos[i]   = run;
        run += c;
    }
    if (t == 1023) g_start[N] = E;
}

// ---------------------------------------------------------------------------
// K5: reorder: place dst[e] into its src-segment slot. 4 edges/thread.
// ---------------------------------------------------------------------------
__global__ void reorder_k(const int* __restrict__ src,
                          const int* __restrict__ dstI, int E)
{
    int i = blockIdx.x * blockDim.x + threadIdx.x;
    int e0 = i * 4;
    if (e0 + 3 < E) {
        int4 s = *reinterpret_cast<const int4*>(&src[e0]);
        int4 d = *reinterpret_cast<const int4*>(&dstI[e0]);
        g_dste[atomicAdd(&g_pos[s.x], 1)] = d.x;
        g_dste[atomicAdd(&g_pos[s.y], 1)] = d.y;
        g_dste[atomicAdd(&g_pos[s.z], 1)] = d.z;
        g_dste[atomicAdd(&g_pos[s.w], 1)] = d.w;
    } else {
        for (int e = e0; e < E; e++)
            g_dste[atomicAdd(&g_pos[src[e]], 1)] = dstI[e];
    }
}

// ---------------------------------------------------------------------------
// K6: per-node logits -> exp, reduce denominators. 8 threads per node
// (cuts the serial MLP chain 8x vs one thread/node).
// ---------------------------------------------------------------------------
__global__ __launch_bounds__(256) void alpha_k(const int* __restrict__ dstI,
                                               const float* __restrict__ eattr,
                                               const float* __restrict__ eW1,
                                               const float* __restrict__ eb1,
                                               const float* __restrict__ eW2,
                                               const float* __restrict__ eb2,
                                               int N)
{
    int gid = blockIdx.x * blockDim.x + threadIdx.x;
    int n   = gid >> 3;
    int sub = gid & 7;
    float ev0 = 0.f, ev1 = 0.f, ev2 = 0.f, ev3 = 0.f;

    if (n < N) {
        int e = g_last[n];
        if (e >= 0) {
            int m = __ldg(&dstI[e]);
            float4 ea = *reinterpret_cast<const float4*>(&eattr[(size_t)e * 4]);
            float vh0 = 0.f, vh1 = 0.f, vh2 = 0.f, vh3 = 0.f;
#pragma unroll
            for (int tt = 0; tt < 4; tt++) {
                int j = sub + 8 * tt;
                float hid = fmaf(ea.x, __ldg(&eW1[j]),
                            fmaf(ea.y, __ldg(&eW1[32 + j]),
                            fmaf(ea.z, __ldg(&eW1[64 + j]),
                            fmaf(ea.w, __ldg(&eW1[96 + j]), __ldg(&eb1[j])))));
                hid = fmaxf(hid, 0.f);
                vh0 = fmaf(hid, __ldg(&eW2[j * 4 + 0]), vh0);
                vh1 = fmaf(hid, __ldg(&eW2[j * 4 + 1]), vh1);
                vh2 = fmaf(hid, __ldg(&eW2[j * 4 + 2]), vh2);
                vh3 = fmaf(hid, __ldg(&eW2[j * 4 + 3]), vh3);
            }
#pragma unroll
            for (int off = 4; off > 0; off >>= 1) {
                vh0 += __shfl_down_sync(0xffffffffu, vh0, off, 8);
                vh1 += __shfl_down_sync(0xffffffffu, vh1, off, 8);
                vh2 += __shfl_down_sync(0xffffffffu, vh2, off, 8);
                vh3 += __shfl_down_sync(0xffffffffu, vh3, off, 8);
            }
            if (sub == 0) {
                float v0 = g_s[n * 4 + 0] + g_d[m * 4 + 0] + vh0 + eb2[0];
                float v1 = g_s[n * 4 + 1] + g_d[m * 4 + 1] + vh1 + eb2[1];
                float v2 = g_s[n * 4 + 2] + g_d[m * 4 + 2] + vh2 + eb2[2];
                float v3 = g_s[n * 4 + 3] + g_d[m * 4 + 3] + vh3 + eb2[3];
                v0 = v0 > 0.f ? v0 : 0.2f * v0;
                v1 = v1 > 0.f ? v1 : 0.2f * v1;
                v2 = v2 > 0.f ? v2 : 0.2f * v2;
                v3 = v3 > 0.f ? v3 : 0.2f * v3;
                ev0 = expf(v0); ev1 = expf(v1); ev2 = expf(v2); ev3 = expf(v3);
                float4 o = make_float4(ev0, ev1, ev2, ev3);
                *reinterpret_cast<float4*>(&g_expv[n * 4]) = o;
            }
        }
    }
    // warp-reduce denominators (nonzero only on sub==0 lanes)
#pragma unroll
    for (int off = 16; off > 0; off >>= 1) {
        ev0 += __shfl_down_sync(0xffffffffu, ev0, off);
        ev1 += __shfl_down_sync(0xffffffffu, ev1, off);
        ev2 += __shfl_down_sync(0xffffffffu, ev2, off);
        ev3 += __shfl_down_sync(0xffffffffu, ev3, off);
    }
    if ((threadIdx.x & 31) == 0) {
        atomicAdd(&g_sum[0], ev0);
        atomicAdd(&g_sum[1], ev1);
        atomicAdd(&g_sum[2], ev2);
        atomicAdd(&g_sum[3], ev3);
    }
}

__global__ void finalize_k()
{
    int h = threadIdx.x;
    if (h < 4) g_inv[h] = 0.25f / g_sum[h];
}

// ---------------------------------------------------------------------------
// K7: segment-sum. One warp per node; NO atomics, single store per row.
// out[n,f] = sum_h alpha[n,h] * (sum_{e in seg(n)} h2[dst_e, h*32+f])
// ---------------------------------------------------------------------------
__global__ __launch_bounds__(256) void segsum_k(float* __restrict__ out, int N)
{
    int gw   = (blockIdx.x * 256 + threadIdx.x) >> 5;
    int lane = threadIdx.x & 31;
    if (gw >= N) return;

    int s0 = g_start[gw];
    int s1 = g_start[gw + 1];

    float acc0 = 0.f, acc1 = 0.f, acc2 = 0.f, acc3 = 0.f;

    for (int base = s0; base < s1; base += 32) {
        int cnt = s1 - base; if (cnt > 32) cnt = 32;
        int me = (lane < cnt) ? __ldg(&g_dste[base + lane]) : 0;
        if (cnt == 32) {
#pragma unroll 8
            for (int j = 0; j < 32; j++) {
                int m = __shfl_sync(0xffffffffu, me, j);
                const __half* hp = g_h2 + (size_t)m * 128;
                acc0 += __half2float(__ldg(&hp[lane]));
                acc1 += __half2float(__ldg(&hp[32 + lane]));
                acc2 += __half2float(__ldg(&hp[64 + lane]));
                acc3 += __half2float(__ldg(&hp[96 + lane]));
            }
        } else {
            for (int j = 0; j < cnt; j++) {
                int m = __shfl_sync(0xffffffffu, me, j);
                const __half* hp = g_h2 + (size_t)m * 128;
                acc0 += __half2float(__ldg(&hp[lane]));
                acc1 += __half2float(__ldg(&hp[32 + lane]));
                acc2 += __half2float(__ldg(&hp[64 + lane]));
                acc3 += __half2float(__ldg(&hp[96 + lane]));
            }
        }
    }

    float4 ev = *reinterpret_cast<const float4*>(&g_expv[gw * 4]);
    float a0 = ev.x * g_inv[0];
    float a1 = ev.y * g_inv[1];
    float a2 = ev.z * g_inv[2];
    float a3 = ev.w * g_inv[3];

    out[(size_t)gw * 32 + lane] = a0 * acc0 + a1 * acc1 + a2 * acc2 + a3 * acc3;
}

// ---------------------------------------------------------------------------
extern "C" void kernel_launch(void* const* d_in, const int* in_sizes, int n_in,
                              void* d_out, int out_size)
{
    const float* x    = (const float*)d_in[0];
    const int*   ei   = (const int*)d_in[1];
    const float* ea   = (const float*)d_in[2];
    const float* W    = (const float*)d_in[3];
    const float* b    = (const float*)d_in[4];
    const float* eW1  = (const float*)d_in[5];
    const float* eb1  = (const float*)d_in[6];
    const float* eW2  = (const float*)d_in[7];
    const float* eb2  = (const float*)d_in[8];
    const float* asrc = (const float*)d_in[9];
    const float* adst = (const float*)d_in[10];
    float* out = (float*)d_out;

    int N = in_sizes[0] / 128;
    int E = in_sizes[1] / 2;
    const int* srcI = ei;
    const int* dstI = ei + E;

    init_k<<<(N + 255) / 256, 256>>>(N);
    gemm_h<<<(N + 63) / 64, 256>>>(x, W, b, asrc, adst, N);
    last_cnt_k<<<((E + 3) / 4 + 255) / 256, 256>>>(srcI, E);
    scan_k<<<1, 1024>>>(N, E);
    reorder_k<<<((E + 3) / 4 + 255) / 256, 256>>>(srcI, dstI, E);
    alpha_k<<<(N * 8 + 255) / 256, 256>>>(dstI, ea, eW1, eb1, eW2, eb2, N);
    finalize_k<<<1, 32>>>();
    segsum_k<<<(N * 32 + 255) / 256, 256>>>(out, N);
}

// round 5
// speedup vs baseline: 1.5101x; 1.5101x over previous
#include <cuda_runtime.h>
#include <cuda_fp16.h>
#include <cstdint>

#define NN 50000
#define NE 1600000

// ---------------- device scratch (no allocation allowed) -------------------
__device__ __half g_h2[NN * 128];      // fp16 projected features
__device__ float  g_s[NN * 4];         // alpha_src per node/head
__device__ float  g_d[NN * 4];         // alpha_dst per node/head
__device__ int    g_last[NN];          // last edge with src==n, else -1
__device__ int    g_cnt[NN];           // out-degree histogram
__device__ int    g_start[NN + 1];     // segment starts
__device__ int    g_pos[NN];           // placement cursors
__device__ int    g_dste[NE];          // dst indices sorted by src
__device__ float  g_expv[NN * 4];      // exp(leaky(logit)); stale for no-edge nodes (unused)
__device__ float  g_sum[4];
__device__ float  g_inv[4];
__device__ __align__(16) unsigned char g_Bsw[128 * 128 * 2];  // W^T fp16, swizzled
__device__ int    g_bsum[256];         // scan block sums

__device__ __forceinline__ uint32_t smem_u32(const void* p) {
    uint32_t a;
    asm("{ .reg .u64 t; cvta.to.shared.u64 t, %1; cvt.u32.u64 %0, t; }" : "=r"(a) : "l"(p));
    return a;
}

// ---------------------------------------------------------------------------
// P0: W -> g_Bsw: B[n][k] = W[k][n] fp16, rows of 256B, 16B-chunk XOR swizzle.
// ---------------------------------------------------------------------------
__global__ void prep_w(const float* __restrict__ W)
{
    int idx = blockIdx.x * 256 + threadIdx.x;          // 8192 total
    if (idx >= 128 * 64) return;
    int n = idx >> 6;                                  // 0..127 (out col)
    int k = (idx & 63) * 2;                            // 0..126 (k pair)
    __half2 p = __floats2half2_rn(__ldg(&W[k * 128 + n]), __ldg(&W[(k + 1) * 128 + n]));
    uint32_t off = (uint32_t)n * 256u
                 + (uint32_t)(((k >> 3) ^ (n & 7)) << 4)
                 + (uint32_t)(k & 7) * 2u;
    *(uint32_t*)(g_Bsw + off) = *(uint32_t*)&p;
}

// ---------------------------------------------------------------------------
// K1: h = x@W + b via mma.sync m16n8k16 (fp16 in, fp32 acc).
// CTA: 256 thr = 8 warps, 128 rows. Warp w: rows w*16..w*16+15, all 128 cols.
// Epilogue: bias, fp16 h2 store, in-register attn dots (quad reduce).
// ---------------------------------------------------------------------------
#define MMA_SMEM 65536

__global__ __launch_bounds__(256, 2)
void mma_h(const float* __restrict__ x, const float* __restrict__ b,
           const float* __restrict__ asrc, const float* __restrict__ adst, int N)
{
    extern __shared__ char smem[];
    const int tid  = threadIdx.x;
    const int wid  = tid >> 5;
    const int lane = tid & 31;
    const int row0 = blockIdx.x * 128;

    // B tile: straight 32KB copy of pre-swizzled image.
    {
        const uint4* s4 = (const uint4*)g_Bsw;
        uint4* d4 = (uint4*)(smem + 32768);
#pragma unroll
        for (int i = 0; i < 8; i++) d4[tid + 256 * i] = s4[tid + 256 * i];
    }
    // A tile: x fp32 -> fp16, swizzled store. Thread t: row t>>1, 64 cols.
    {
        int r  = tid >> 1;
        int c0 = (tid & 1) * 64;
        int rr = row0 + r; if (rr >= N) rr = N - 1;
        const float4* xr = (const float4*)(x + (size_t)rr * 128 + c0);
        char* rowbase = smem + r * 256;
#pragma unroll
        for (int q = 0; q < 16; q++) {
            float4 v = __ldg(&xr[q]);
            int c = c0 + q * 4;
            __half2 h0 = __floats2half2_rn(v.x, v.y);
            __half2 h1 = __floats2half2_rn(v.z, v.w);
            uint2 pk;
            pk.x = *(uint32_t*)&h0;
            pk.y = *(uint32_t*)&h1;
            int off = (((c >> 3) ^ (r & 7)) << 4) + (c & 7) * 2;
            *(uint2*)(rowbase + off) = pk;
        }
    }
    __syncthreads();

    const uint32_t smA = smem_u32(smem);
    const uint32_t smB = smA + 32768;

    float acc[16][4];
#pragma unroll
    for (int nt = 0; nt < 16; nt++)
#pragma unroll
        for (int j = 0; j < 4; j++) acc[nt][j] = 0.f;

    // ldmatrix lane addressing
    const int sub  = lane & 7;
    const int amat = lane >> 3;                       // 0..3
    const int arow = wid * 16 + sub + (amat & 1) * 8; // A row for this lane
    const int achk = amat >> 1;                       // +0 / +1 on chunk
    const int bchk = (lane >> 3) & 1;                 // B chunk select (lanes 0-15 used)

#pragma unroll
    for (int k = 0; k < 8; k++) {
        uint32_t a0, a1, a2, a3;
        {
            uint32_t addr = smA + arow * 256 + ((((k * 2 + achk)) ^ (arow & 7)) << 4);
            asm volatile("ldmatrix.sync.aligned.m8n8.x4.shared.b16 {%0,%1,%2,%3}, [%4];"
                         : "=r"(a0), "=r"(a1), "=r"(a2), "=r"(a3) : "r"(addr));
        }
#pragma unroll
        for (int nt = 0; nt < 16; nt++) {
            int brow = nt * 8 + sub;
            uint32_t baddr = smB + brow * 256 + ((((k * 2 + bchk)) ^ (brow & 7)) << 4);
            uint32_t b0, b1;
            asm volatile("ldmatrix.sync.aligned.m8n8.x2.shared.b16 {%0,%1}, [%2];"
                         : "=r"(b0), "=r"(b1) : "r"(baddr));
            asm volatile(
                "mma.sync.aligned.m16n8k16.row.col.f32.f16.f16.f32 "
                "{%0,%1,%2,%3}, {%4,%5,%6,%7}, {%8,%9}, {%0,%1,%2,%3};"
                : "+f"(acc[nt][0]), "+f"(acc[nt][1]), "+f"(acc[nt][2]), "+f"(acc[nt][3])
                : "r"(a0), "r"(a1), "r"(a2), "r"(a3), "r"(b0), "r"(b1));
        }
    }

    // Epilogue. Thread owns rows r0 (d0,d1) and r1=r0+8 (d2,d3),
    // cols c0 = nt*8 + tIG*2, c0+1 for nt = 0..15. head = nt>>2.
    const int gID = lane >> 2;
    const int tIG = lane & 3;
    const int r0  = row0 + wid * 16 + gID;
    const int r1  = r0 + 8;

    float ps0[4], pd0[4], ps1[4], pd1[4];
#pragma unroll
    for (int h = 0; h < 4; h++) { ps0[h] = pd0[h] = ps1[h] = pd1[h] = 0.f; }
    uint32_t pk0[16], pk1[16];

#pragma unroll
    for (int nt = 0; nt < 16; nt++) {
        int c0 = nt * 8 + tIG * 2;
        float bb0 = __ldg(&b[c0]),    bb1 = __ldg(&b[c0 + 1]);
        float as0 = __ldg(&asrc[c0]), as1 = __ldg(&asrc[c0 + 1]);
        float ad0 = __ldg(&adst[c0]), ad1 = __ldg(&adst[c0 + 1]);
        float v00 = acc[nt][0] + bb0, v01 = acc[nt][1] + bb1;  // row r0
        float v10 = acc[nt][2] + bb0, v11 = acc[nt][3] + bb1;  // row r1
        int h = nt >> 2;
        ps0[h] += v00 * as0 + v01 * as1;
        pd0[h] += v00 * ad0 + v01 * ad1;
        ps1[h] += v10 * as0 + v11 * as1;
        pd1[h] += v10 * ad0 + v11 * ad1;
        __half2 q0 = __floats2half2_rn(v00, v01);
        __half2 q1 = __floats2half2_rn(v10, v11);
        pk0[nt] = *(uint32_t*)&q0;
        pk1[nt] = *(uint32_t*)&q1;
    }
#pragma unroll
    for (int h = 0; h < 4; h++) {
        ps0[h] += __shfl_down_sync(0xffffffffu, ps0[h], 2, 4);
        ps0[h] += __shfl_down_sync(0xffffffffu, ps0[h], 1, 4);
        pd0[h] += __shfl_down_sync(0xffffffffu, pd0[h], 2, 4);
        pd0[h] += __shfl_down_sync(0xffffffffu, pd0[h], 1, 4);
        ps1[h] += __shfl_down_sync(0xffffffffu, ps1[h], 2, 4);
        ps1[h] += __shfl_down_sync(0xffffffffu, ps1[h], 1, 4);
        pd1[h] += __shfl_down_sync(0xffffffffu, pd1[h], 2, 4);
        pd1[h] += __shfl_down_sync(0xffffffffu, pd1[h], 1, 4);
    }
    if (r0 < N) {
#pragma unroll
        for (int nt = 0; nt < 16; nt++)
            *(uint32_t*)&g_h2[(size_t)r0 * 128 + nt * 8 + tIG * 2] = pk0[nt];
        if (tIG == 0) {
#pragma unroll
            for (int h = 0; h < 4; h++) {
                g_s[r0 * 4 + h] = ps0[h];
                g_d[r0 * 4 + h] = pd0[h];
            }
        }
    }
    if (r1 < N) {
#pragma unroll
        for (int nt = 0; nt < 16; nt++)
            *(uint32_t*)&g_h2[(size_t)r1 * 128 + nt * 8 + tIG * 2] = pk1[nt];
        if (tIG == 0) {
#pragma unroll
            for (int h = 0; h < 4; h++) {
                g_s[r1 * 4 + h] = ps1[h];
                g_d[r1 * 4 + h] = pd1[h];
            }
        }
    }
}

// ---------------------------------------------------------------------------
// K2: init per-launch state.
// ---------------------------------------------------------------------------
__global__ void init_k(int N)
{
    int i = blockIdx.x * blockDim.x + threadIdx.x;
    if (i < N) { g_last[i] = -1; g_cnt[i] = 0; }
    if (i < 4) g_sum[i] = 0.f;
}

// ---------------------------------------------------------------------------
// K3: fused last[src]=max(e) + degree histogram. 4 edges/thread.
// ---------------------------------------------------------------------------
__global__ void last_cnt_k(const int* __restrict__ src, int E)
{
    int i = blockIdx.x * blockDim.x + threadIdx.x;
    int e0 = i * 4;
    if (e0 + 3 < E) {
        int4 s = *reinterpret_cast<const int4*>(&src[e0]);
        atomicMax(&g_last[s.x], e0);
        atomicMax(&g_last[s.y], e0 + 1);
        atomicMax(&g_last[s.z], e0 + 2);
        atomicMax(&g_last[s.w], e0 + 3);
        atomicAdd(&g_cnt[s.x], 1);
        atomicAdd(&g_cnt[s.y], 1);
        atomicAdd(&g_cnt[s.z], 1);
        atomicAdd(&g_cnt[s.w], 1);
    } else {
        for (int e = e0; e < E; e++) {
            int s = src[e];
            atomicMax(&g_last[s], e);
            atomicAdd(&g_cnt[s], 1);
        }
    }
}

// ---------------------------------------------------------------------------
// Scan, 3 phases (multi-block).
// ---------------------------------------------------------------------------
__device__ __forceinline__ int block_incl_scan(int v, int t)
{
    __shared__ int ws[8];
    int lane = t & 31, w = t >> 5;
    int xv = v;
#pragma unroll
    for (int o = 1; o < 32; o <<= 1) {
        int u = __shfl_up_sync(0xffffffffu, xv, o);
        if (lane >= o) xv += u;
    }
    if (lane == 31) ws[w] = xv;
    __syncthreads();
    if (t < 8) {
        int y = ws[t];
#pragma unroll
        for (int o = 1; o < 8; o <<= 1) {
            int u = __shfl_up_sync(0xffu, y, o);
            if (t >= o) y += u;
        }
        ws[t] = y;
    }
    __syncthreads();
    return xv + (w > 0 ? ws[w - 1] : 0);
}

__global__ __launch_bounds__(256) void scan1(int N)
{
    int i = blockIdx.x * 256 + threadIdx.x;
    int v = (i < N) ? g_cnt[i] : 0;
    int incl = block_incl_scan(v, threadIdx.x);
    if (threadIdx.x == 255) g_bsum[blockIdx.x] = incl;
}

__global__ __launch_bounds__(256) void scan2(int nb, int N, int E)
{
    int t = threadIdx.x;
    int v = (t < nb) ? g_bsum[t] : 0;
    int incl = block_incl_scan(v, t);
    if (t < nb) g_bsum[t] = incl - v;     // exclusive
    if (t == 0) g_start[N] = E;
}

__global__ __launch_bounds__(256) void scan3(int N)
{
    int i = blockIdx.x * 256 + threadIdx.x;
    int v = (i < N) ? g_cnt[i] : 0;
    int incl = block_incl_scan(v, threadIdx.x);
    if (i < N) {
        int e = incl - v + g_bsum[blockIdx.x];
        g_start[i] = e;
        g_pos[i]   = e;
    }
}

// ---------------------------------------------------------------------------
// K5: reorder edges by src segment.
// ---------------------------------------------------------------------------
__global__ void reorder_k(const int* __restrict__ src,
                          const int* __restrict__ dstI, int E)
{
    int i = blockIdx.x * blockDim.x + threadIdx.x;
    int e0 = i * 4;
    if (e0 + 3 < E) {
        int4 s = *reinterpret_cast<const int4*>(&src[e0]);
        int4 d = *reinterpret_cast<const int4*>(&dstI[e0]);
        g_dste[atomicAdd(&g_pos[s.x], 1)] = d.x;
        g_dste[atomicAdd(&g_pos[s.y], 1)] = d.y;
        g_dste[atomicAdd(&g_pos[s.z], 1)] = d.z;
        g_dste[atomicAdd(&g_pos[s.w], 1)] = d.w;
    } else {
        for (int e = e0; e < E; e++)
            g_dste[atomicAdd(&g_pos[src[e]], 1)] = dstI[e];
    }
}

// ---------------------------------------------------------------------------
// K6: per-node logits -> exp, reduce denominators (8 threads/node).
// ---------------------------------------------------------------------------
__global__ __launch_bounds__(256) void alpha_k(const int* __restrict__ dstI,
                                               const float* __restrict__ eattr,
                                               const float* __restrict__ eW1,
                                               const float* __restrict__ eb1,
                                               const float* __restrict__ eW2,
                                               const float* __restrict__ eb2,
                                               int N)
{
    int gid = blockIdx.x * blockDim.x + threadIdx.x;
    int n   = gid >> 3;
    int sub = gid & 7;
    float ev0 = 0.f, ev1 = 0.f, ev2 = 0.f, ev3 = 0.f;

    if (n < N) {
        int e = g_last[n];
        if (e >= 0) {
            int m = __ldg(&dstI[e]);
            float4 ea = *reinterpret_cast<const float4*>(&eattr[(size_t)e * 4]);
            float vh0 = 0.f, vh1 = 0.f, vh2 = 0.f, vh3 = 0.f;
#pragma unroll
            for (int tt = 0; tt < 4; tt++) {
                int j = sub + 8 * tt;
                float hid = fmaf(ea.x, __ldg(&eW1[j]),
                            fmaf(ea.y, __ldg(&eW1[32 + j]),
                            fmaf(ea.z, __ldg(&eW1[64 + j]),
                            fmaf(ea.w, __ldg(&eW1[96 + j]), __ldg(&eb1[j])))));
                hid = fmaxf(hid, 0.f);
                vh0 = fmaf(hid, __ldg(&eW2[j * 4 + 0]), vh0);
                vh1 = fmaf(hid, __ldg(&eW2[j * 4 + 1]), vh1);
                vh2 = fmaf(hid, __ldg(&eW2[j * 4 + 2]), vh2);
                vh3 = fmaf(hid, __ldg(&eW2[j * 4 + 3]), vh3);
            }
#pragma unroll
            for (int off = 4; off > 0; off >>= 1) {
                vh0 += __shfl_down_sync(0xffffffffu, vh0, off, 8);
                vh1 += __shfl_down_sync(0xffffffffu, vh1, off, 8);
                vh2 += __shfl_down_sync(0xffffffffu, vh2, off, 8);
                vh3 += __shfl_down_sync(0xffffffffu, vh3, off, 8);
            }
            if (sub == 0) {
                float v0 = g_s[n * 4 + 0] + g_d[m * 4 + 0] + vh0 + __ldg(&eb2[0]);
                float v1 = g_s[n * 4 + 1] + g_d[m * 4 + 1] + vh1 + __ldg(&eb2[1]);
                float v2 = g_s[n * 4 + 2] + g_d[m * 4 + 2] + vh2 + __ldg(&eb2[2]);
                float v3 = g_s[n * 4 + 3] + g_d[m * 4 + 3] + vh3 + __ldg(&eb2[3]);
                v0 = v0 > 0.f ? v0 : 0.2f * v0;
                v1 = v1 > 0.f ? v1 : 0.2f * v1;
                v2 = v2 > 0.f ? v2 : 0.2f * v2;
                v3 = v3 > 0.f ? v3 : 0.2f * v3;
                ev0 = expf(v0); ev1 = expf(v1); ev2 = expf(v2); ev3 = expf(v3);
                *reinterpret_cast<float4*>(&g_expv[n * 4]) = make_float4(ev0, ev1, ev2, ev3);
            }
        }
    }
#pragma unroll
    for (int off = 16; off > 0; off >>= 1) {
        ev0 += __shfl_down_sync(0xffffffffu, ev0, off);
        ev1 += __shfl_down_sync(0xffffffffu, ev1, off);
        ev2 += __shfl_down_sync(0xffffffffu, ev2, off);
        ev3 += __shfl_down_sync(0xffffffffu, ev3, off);
    }
    if ((threadIdx.x & 31) == 0) {
        atomicAdd(&g_sum[0], ev0);
        atomicAdd(&g_sum[1], ev1);
        atomicAdd(&g_sum[2], ev2);
        atomicAdd(&g_sum[3], ev3);
    }
}

__global__ void finalize_k()
{
    int h = threadIdx.x;
    if (h < 4) g_inv[h] = 0.25f / g_sum[h];
}

// ---------------------------------------------------------------------------
// K7: segment-sum, one warp/node, half2 gathers, no atomics.
// ---------------------------------------------------------------------------
__global__ __launch_bounds__(256) void segsum_k(float* __restrict__ out, int N)
{
    int gw   = (blockIdx.x * 256 + threadIdx.x) >> 5;
    int lane = threadIdx.x & 31;
    if (gw >= N) return;

    int s0 = g_start[gw];
    int s1 = g_start[gw + 1];

    float2 accA = make_float2(0.f, 0.f);
    float2 accB = make_float2(0.f, 0.f);

    for (int base = s0; base < s1; base += 32) {
        int cnt = s1 - base; if (cnt > 32) cnt = 32;
        int me = (lane < cnt) ? __ldg(&g_dste[base + lane]) : 0;
        for (int j = 0; j < cnt; j++) {
            int m = __shfl_sync(0xffffffffu, me, j);
            const __half2* hp = (const __half2*)(g_h2 + (size_t)m * 128);
            float2 fa = __half22float2(__ldg(&hp[lane]));
            float2 fb = __half22float2(__ldg(&hp[32 + lane]));
            accA.x += fa.x; accA.y += fa.y;
            accB.x += fb.x; accB.y += fb.y;
        }
    }

    float4 ev = *reinterpret_cast<const float4*>(&g_expv[gw * 4]);
    float a0 = ev.x * g_inv[0];
    float a1 = ev.y * g_inv[1];
    float a2 = ev.z * g_inv[2];
    float a3 = ev.w * g_inv[3];

    float aA = (lane < 16) ? a0 : a1;
    float aB = (lane < 16) ? a2 : a3;
    float px = aA * accA.x + aB * accB.x;
    float py = aA * accA.y + aB * accB.y;
    px += __shfl_down_sync(0xffffffffu, px, 16);
    py += __shfl_down_sync(0xffffffffu, py, 16);
    if (lane < 16)
        *reinterpret_cast<float2*>(&out[(size_t)gw * 32 + 2 * lane]) = make_float2(px, py);
}

// ---------------------------------------------------------------------------
extern "C" void kernel_launch(void* const* d_in, const int* in_sizes, int n_in,
                              void* d_out, int out_size)
{
    const float* x    = (const float*)d_in[0];
    const int*   ei   = (const int*)d_in[1];
    const float* ea   = (const float*)d_in[2];
    const float* W    = (const float*)d_in[3];
    const float* b    = (const float*)d_in[4];
    const float* eW1  = (const float*)d_in[5];
    const float* eb1  = (const float*)d_in[6];
    const float* eW2  = (const float*)d_in[7];
    const float* eb2  = (const float*)d_in[8];
    const float* asrc = (const float*)d_in[9];
    const float* adst = (const float*)d_in[10];
    float* out = (float*)d_out;

    int N = in_sizes[0] / 128;
    int E = in_sizes[1] / 2;
    const int* srcI = ei;
    const int* dstI = ei + E;
    int nb = (N + 255) / 256;

    cudaFuncSetAttribute(mma_h, cudaFuncAttributeMaxDynamicSharedMemorySize, MMA_SMEM);

    prep_w<<<32, 256>>>(W);
    init_k<<<(N + 255) / 256, 256>>>(N);
    last_cnt_k<<<((E + 3) / 4 + 255) / 256, 256>>>(srcI, E);
    scan1<<<nb, 256>>>(N);
    scan2<<<1, 256>>>(nb, N, E);
    scan3<<<nb, 256>>>(N);
    reorder_k<<<((E + 3) / 4 + 255) / 256, 256>>>(srcI, dstI, E);
    mma_h<<<(N + 127) / 128, 256, MMA_SMEM>>>(x, b, asrc, adst, N);
    alpha_k<<<(N * 8 + 255) / 256, 256>>>(dstI, ea, eW1, eb1, eW2, eb2, N);
    finalize_k<<<1, 32>>>();
    segsum_k<<<(N * 32 + 255) / 256, 256>>>(out, N);
}

// round 6
// speedup vs baseline: 1.6190x; 1.0721x over previous
#include <cuda_runtime.h>
#include <cuda_fp16.h>
#include <cstdint>

#define NN 50000
#define NE 1600000

// ---------------- device scratch (no allocation allowed) -------------------
__device__ __half g_h2[NN * 128];      // fp16 projected features
__device__ float  g_s[NN * 4];         // alpha_src per node/head
__device__ float  g_d[NN * 4];         // alpha_dst per node/head
__device__ int    g_last[NN];          // last edge with src==n, else -1
__device__ int    g_cnt[NN];           // out-degree histogram
__device__ int    g_start[NN + 1];     // segment starts
__device__ int    g_pos[NN];           // placement cursors
__device__ int    g_dste[NE];          // dst indices sorted by src
__device__ float  g_expv[NN * 4];      // exp(leaky(logit)) per valid node/head
__device__ float  g_sum[4];
__device__ __align__(16) unsigned char g_Bsw[128 * 128 * 2];  // W^T fp16, swizzled
__device__ int    g_bsum[256];         // scan block sums

__device__ __forceinline__ uint32_t smem_u32(const void* p) {
    uint32_t a;
    asm("{ .reg .u64 t; cvta.to.shared.u64 t, %1; cvt.u32.u64 %0, t; }" : "=r"(a) : "l"(p));
    return a;
}

// ---------------- streams/events for fork-join (created pre-main) ----------
static cudaStream_t g_side = nullptr;
static cudaEvent_t  g_evF  = nullptr;
static cudaEvent_t  g_evJ  = nullptr;
namespace {
struct CudaInit {
    CudaInit() {
        cudaStreamCreateWithFlags(&g_side, cudaStreamNonBlocking);
        cudaEventCreateWithFlags(&g_evF, cudaEventDisableTiming);
        cudaEventCreateWithFlags(&g_evJ, cudaEventDisableTiming);
    }
} g_cudainit;
}

// ---------------------------------------------------------------------------
// P0: W -> g_Bsw: B[n][k] = W[k][n] fp16, rows of 256B, 16B-chunk XOR swizzle.
// ---------------------------------------------------------------------------
__global__ void prep_w(const float* __restrict__ W)
{
    int idx = blockIdx.x * 256 + threadIdx.x;          // 8192 total
    if (idx >= 128 * 64) return;
    int n = idx >> 6;
    int k = (idx & 63) * 2;
    __half2 p = __floats2half2_rn(__ldg(&W[k * 128 + n]), __ldg(&W[(k + 1) * 128 + n]));
    uint32_t off = (uint32_t)n * 256u
                 + (uint32_t)(((k >> 3) ^ (n & 7)) << 4)
                 + (uint32_t)(k & 7) * 2u;
    *(uint32_t*)(g_Bsw + off) = *(uint32_t*)&p;
}

// ---------------------------------------------------------------------------
// K1: h = x@W + b via mma.sync m16n8k16 (fp16 in, fp32 acc).
// ---------------------------------------------------------------------------
#define MMA_SMEM 65536

__global__ __launch_bounds__(256, 2)
void mma_h(const float* __restrict__ x, const float* __restrict__ b,
           const float* __restrict__ asrc, const float* __restrict__ adst, int N)
{
    extern __shared__ char smem[];
    const int tid  = threadIdx.x;
    const int wid  = tid >> 5;
    const int lane = tid & 31;
    const int row0 = blockIdx.x * 128;

    {
        const uint4* s4 = (const uint4*)g_Bsw;
        uint4* d4 = (uint4*)(smem + 32768);
#pragma unroll
        for (int i = 0; i < 8; i++) d4[tid + 256 * i] = s4[tid + 256 * i];
    }
    {
        int r  = tid >> 1;
        int c0 = (tid & 1) * 64;
        int rr = row0 + r; if (rr >= N) rr = N - 1;
        const float4* xr = (const float4*)(x + (size_t)rr * 128 + c0);
        char* rowbase = smem + r * 256;
#pragma unroll
        for (int q = 0; q < 16; q++) {
            float4 v = __ldg(&xr[q]);
            int c = c0 + q * 4;
            __half2 h0 = __floats2half2_rn(v.x, v.y);
            __half2 h1 = __floats2half2_rn(v.z, v.w);
            uint2 pk;
            pk.x = *(uint32_t*)&h0;
            pk.y = *(uint32_t*)&h1;
            int off = (((c >> 3) ^ (r & 7)) << 4) + (c & 7) * 2;
            *(uint2*)(rowbase + off) = pk;
        }
    }
    __syncthreads();

    const uint32_t smA = smem_u32(smem);
    const uint32_t smB = smA + 32768;

    float acc[16][4];
#pragma unroll
    for (int nt = 0; nt < 16; nt++)
#pragma unroll
        for (int j = 0; j < 4; j++) acc[nt][j] = 0.f;

    const int sub  = lane & 7;
    const int amat = lane >> 3;
    const int arow = wid * 16 + sub + (amat & 1) * 8;
    const int achk = amat >> 1;
    const int bchk = (lane >> 3) & 1;

#pragma unroll
    for (int k = 0; k < 8; k++) {
        uint32_t a0, a1, a2, a3;
        {
            uint32_t addr = smA + arow * 256 + ((((k * 2 + achk)) ^ (arow & 7)) << 4);
            asm volatile("ldmatrix.sync.aligned.m8n8.x4.shared.b16 {%0,%1,%2,%3}, [%4];"
                         : "=r"(a0), "=r"(a1), "=r"(a2), "=r"(a3) : "r"(addr));
        }
#pragma unroll
        for (int nt = 0; nt < 16; nt++) {
            int brow = nt * 8 + sub;
            uint32_t baddr = smB + brow * 256 + ((((k * 2 + bchk)) ^ (brow & 7)) << 4);
            uint32_t b0, b1;
            asm volatile("ldmatrix.sync.aligned.m8n8.x2.shared.b16 {%0,%1}, [%2];"
                         : "=r"(b0), "=r"(b1) : "r"(baddr));
            asm volatile(
                "mma.sync.aligned.m16n8k16.row.col.f32.f16.f16.f32 "
                "{%0,%1,%2,%3}, {%4,%5,%6,%7}, {%8,%9}, {%0,%1,%2,%3};"
                : "+f"(acc[nt][0]), "+f"(acc[nt][1]), "+f"(acc[nt][2]), "+f"(acc[nt][3])
                : "r"(a0), "r"(a1), "r"(a2), "r"(a3), "r"(b0), "r"(b1));
        }
    }

    const int gID = lane >> 2;
    const int tIG = lane & 3;
    const int r0  = row0 + wid * 16 + gID;
    const int r1  = r0 + 8;

    float ps0[4], pd0[4], ps1[4], pd1[4];
#pragma unroll
    for (int h = 0; h < 4; h++) { ps0[h] = pd0[h] = ps1[h] = pd1[h] = 0.f; }
    uint32_t pk0[16], pk1[16];

#pragma unroll
    for (int nt = 0; nt < 16; nt++) {
        int c0 = nt * 8 + tIG * 2;
        float bb0 = __ldg(&b[c0]),    bb1 = __ldg(&b[c0 + 1]);
        float as0 = __ldg(&asrc[c0]), as1 = __ldg(&asrc[c0 + 1]);
        float ad0 = __ldg(&adst[c0]), ad1 = __ldg(&adst[c0 + 1]);
        float v00 = acc[nt][0] + bb0, v01 = acc[nt][1] + bb1;
        float v10 = acc[nt][2] + bb0, v11 = acc[nt][3] + bb1;
        int h = nt >> 2;
        ps0[h] += v00 * as0 + v01 * as1;
        pd0[h] += v00 * ad0 + v01 * ad1;
        ps1[h] += v10 * as0 + v11 * as1;
        pd1[h] += v10 * ad0 + v11 * ad1;
        __half2 q0 = __floats2half2_rn(v00, v01);
        __half2 q1 = __floats2half2_rn(v10, v11);
        pk0[nt] = *(uint32_t*)&q0;
        pk1[nt] = *(uint32_t*)&q1;
    }
#pragma unroll
    for (int h = 0; h < 4; h++) {
        ps0[h] += __shfl_down_sync(0xffffffffu, ps0[h], 2, 4);
        ps0[h] += __shfl_down_sync(0xffffffffu, ps0[h], 1, 4);
        pd0[h] += __shfl_down_sync(0xffffffffu, pd0[h], 2, 4);
        pd0[h] += __shfl_down_sync(0xffffffffu, pd0[h], 1, 4);
        ps1[h] += __shfl_down_sync(0xffffffffu, ps1[h], 2, 4);
        ps1[h] += __shfl_down_sync(0xffffffffu, ps1[h], 1, 4);
        pd1[h] += __shfl_down_sync(0xffffffffu, pd1[h], 2, 4);
        pd1[h] += __shfl_down_sync(0xffffffffu, pd1[h], 1, 4);
    }
    if (r0 < N) {
#pragma unroll
        for (int nt = 0; nt < 16; nt++)
            *(uint32_t*)&g_h2[(size_t)r0 * 128 + nt * 8 + tIG * 2] = pk0[nt];
        if (tIG == 0) {
#pragma unroll
            for (int h = 0; h < 4; h++) {
                g_s[r0 * 4 + h] = ps0[h];
                g_d[r0 * 4 + h] = pd0[h];
            }
        }
    }
    if (r1 < N) {
#pragma unroll
        for (int nt = 0; nt < 16; nt++)
            *(uint32_t*)&g_h2[(size_t)r1 * 128 + nt * 8 + tIG * 2] = pk1[nt];
        if (tIG == 0) {
#pragma unroll
            for (int h = 0; h < 4; h++) {
                g_s[r1 * 4 + h] = ps1[h];
                g_d[r1 * 4 + h] = pd1[h];
            }
        }
    }
}

// ---------------------------------------------------------------------------
__global__ void init_k(int N)
{
    int i = blockIdx.x * blockDim.x + threadIdx.x;
    if (i < N) { g_last[i] = -1; g_cnt[i] = 0; }
    if (i < 4) g_sum[i] = 0.f;
}

__global__ void last_cnt_k(const int* __restrict__ src, int E)
{
    int i = blockIdx.x * blockDim.x + threadIdx.x;
    int e0 = i * 4;
    if (e0 + 3 < E) {
        int4 s = *reinterpret_cast<const int4*>(&src[e0]);
        atomicMax(&g_last[s.x], e0);
        atomicMax(&g_last[s.y], e0 + 1);
        atomicMax(&g_last[s.z], e0 + 2);
        atomicMax(&g_last[s.w], e0 + 3);
        atomicAdd(&g_cnt[s.x], 1);
        atomicAdd(&g_cnt[s.y], 1);
        atomicAdd(&g_cnt[s.z], 1);
        atomicAdd(&g_cnt[s.w], 1);
    } else {
        for (int e = e0; e < E; e++) {
            int s = src[e];
            atomicMax(&g_last[s], e);
            atomicAdd(&g_cnt[s], 1);
        }
    }
}

// ---------------------------------------------------------------------------
// Scan, 3 phases.
// ---------------------------------------------------------------------------
__device__ __forceinline__ int block_incl_scan(int v, int t)
{
    __shared__ int ws[8];
    int lane = t & 31, w = t >> 5;
    int xv = v;
#pragma unroll
    for (int o = 1; o < 32; o <<= 1) {
        int u = __shfl_up_sync(0xffffffffu, xv, o);
        if (lane >= o) xv += u;
    }
    if (lane == 31) ws[w] = xv;
    __syncthreads();
    if (t < 8) {
        int y = ws[t];
#pragma unroll
        for (int o = 1; o < 8; o <<= 1) {
            int u = __shfl_up_sync(0xffu, y, o);
            if (t >= o) y += u;
        }
        ws[t] = y;
    }
    __syncthreads();
    return xv + (w > 0 ? ws[w - 1] : 0);
}

__global__ __launch_bounds__(256) void scan1(int N)
{
    int i = blockIdx.x * 256 + threadIdx.x;
    int v = (i < N) ? g_cnt[i] : 0;
    int incl = block_incl_scan(v, threadIdx.x);
    if (threadIdx.x == 255) g_bsum[blockIdx.x] = incl;
}

__global__ __launch_bounds__(256) void scan2(int nb, int N, int E)
{
    int t = threadIdx.x;
    int v = (t < nb) ? g_bsum[t] : 0;
    int incl = block_incl_scan(v, t);
    if (t < nb) g_bsum[t] = incl - v;
    if (t == 0) g_start[N] = E;
}

__global__ __launch_bounds__(256) void scan3(int N)
{
    int i = blockIdx.x * 256 + threadIdx.x;
    int v = (i < N) ? g_cnt[i] : 0;
    int incl = block_incl_scan(v, threadIdx.x);
    if (i < N) {
        int e = incl - v + g_bsum[blockIdx.x];
        g_start[i] = e;
        g_pos[i]   = e;
    }
}

// ---------------------------------------------------------------------------
__global__ void reorder_k(const int* __restrict__ src,
                          const int* __restrict__ dstI, int E)
{
    int i = blockIdx.x * blockDim.x + threadIdx.x;
    int e0 = i * 4;
    if (e0 + 3 < E) {
        int4 s = *reinterpret_cast<const int4*>(&src[e0]);
        int4 d = *reinterpret_cast<const int4*>(&dstI[e0]);
        g_dste[atomicAdd(&g_pos[s.x], 1)] = d.x;
        g_dste[atomicAdd(&g_pos[s.y], 1)] = d.y;
        g_dste[atomicAdd(&g_pos[s.z], 1)] = d.z;
        g_dste[atomicAdd(&g_pos[s.w], 1)] = d.w;
    } else {
        for (int e = e0; e < E; e++)
            g_dste[atomicAdd(&g_pos[src[e]], 1)] = dstI[e];
    }
}

// ---------------------------------------------------------------------------
// K6: per-node logits -> exp, reduce denominators (8 threads/node).
// ---------------------------------------------------------------------------
__global__ __launch_bounds__(256) void alpha_k(const int* __restrict__ dstI,
                                               const float* __restrict__ eattr,
                                               const float* __restrict__ eW1,
                                               const float* __restrict__ eb1,
                                               const float* __restrict__ eW2,
                                               const float* __restrict__ eb2,
                                               int N)
{
    int gid = blockIdx.x * blockDim.x + threadIdx.x;
    int n   = gid >> 3;
    int sub = gid & 7;
    float ev0 = 0.f, ev1 = 0.f, ev2 = 0.f, ev3 = 0.f;

    if (n < N) {
        int e = g_last[n];
        if (e >= 0) {
            int m = __ldg(&dstI[e]);
            float4 ea = *reinterpret_cast<const float4*>(&eattr[(size_t)e * 4]);
            float vh0 = 0.f, vh1 = 0.f, vh2 = 0.f, vh3 = 0.f;
#pragma unroll
            for (int tt = 0; tt < 4; tt++) {
                int j = sub + 8 * tt;
                float hid = fmaf(ea.x, __ldg(&eW1[j]),
                            fmaf(ea.y, __ldg(&eW1[32 + j]),
                            fmaf(ea.z, __ldg(&eW1[64 + j]),
                            fmaf(ea.w, __ldg(&eW1[96 + j]), __ldg(&eb1[j])))));
                hid = fmaxf(hid, 0.f);
                vh0 = fmaf(hid, __ldg(&eW2[j * 4 + 0]), vh0);
                vh1 = fmaf(hid, __ldg(&eW2[j * 4 + 1]), vh1);
                vh2 = fmaf(hid, __ldg(&eW2[j * 4 + 2]), vh2);
                vh3 = fmaf(hid, __ldg(&eW2[j * 4 + 3]), vh3);
            }
#pragma unroll
            for (int off = 4; off > 0; off >>= 1) {
                vh0 += __shfl_down_sync(0xffffffffu, vh0, off, 8);
                vh1 += __shfl_down_sync(0xffffffffu, vh1, off, 8);
                vh2 += __shfl_down_sync(0xffffffffu, vh2, off, 8);
                vh3 += __shfl_down_sync(0xffffffffu, vh3, off, 8);
            }
            if (sub == 0) {
                float v0 = g_s[n * 4 + 0] + g_d[m * 4 + 0] + vh0 + __ldg(&eb2[0]);
                float v1 = g_s[n * 4 + 1] + g_d[m * 4 + 1] + vh1 + __ldg(&eb2[1]);
                float v2 = g_s[n * 4 + 2] + g_d[m * 4 + 2] + vh2 + __ldg(&eb2[2]);
                float v3 = g_s[n * 4 + 3] + g_d[m * 4 + 3] + vh3 + __ldg(&eb2[3]);
                v0 = v0 > 0.f ? v0 : 0.2f * v0;
                v1 = v1 > 0.f ? v1 : 0.2f * v1;
                v2 = v2 > 0.f ? v2 : 0.2f * v2;
                v3 = v3 > 0.f ? v3 : 0.2f * v3;
                ev0 = expf(v0); ev1 = expf(v1); ev2 = expf(v2); ev3 = expf(v3);
                *reinterpret_cast<float4*>(&g_expv[n * 4]) = make_float4(ev0, ev1, ev2, ev3);
            }
        }
    }
#pragma unroll
    for (int off = 16; off > 0; off >>= 1) {
        ev0 += __shfl_down_sync(0xffffffffu, ev0, off);
        ev1 += __shfl_down_sync(0xffffffffu, ev1, off);
        ev2 += __shfl_down_sync(0xffffffffu, ev2, off);
        ev3 += __shfl_down_sync(0xffffffffu, ev3, off);
    }
    if ((threadIdx.x & 31) == 0) {
        atomicAdd(&g_sum[0], ev0);
        atomicAdd(&g_sum[1], ev1);
        atomicAdd(&g_sum[2], ev2);
        atomicAdd(&g_sum[3], ev3);
    }
}

// ---------------------------------------------------------------------------
// K7: segment-sum, one warp/node, 2 edges/iter, uint4 gathers, no atomics.
// Lane layout: half = lane>>4 selects edge parity; l16 = lane&15 covers
// cols 8*l16 .. 8*l16+7 of the gathered row (head = l16>>2).
// ---------------------------------------------------------------------------
__global__ __launch_bounds__(256) void segsum_k(float* __restrict__ out, int N)
{
    int gw   = (blockIdx.x * 256 + threadIdx.x) >> 5;
    int lane = threadIdx.x & 31;
    if (gw >= N) return;

    const int s0 = g_start[gw];
    const int s1 = g_start[gw + 1];
    const int half = lane >> 4;
    const int l16  = lane & 15;

    float2 acc0 = make_float2(0.f, 0.f), acc1 = make_float2(0.f, 0.f);
    float2 acc2 = make_float2(0.f, 0.f), acc3 = make_float2(0.f, 0.f);

    for (int base = s0; base < s1; base += 32) {
        int cnt = s1 - base; if (cnt > 32) cnt = 32;
        int me = (lane < cnt) ? __ldg(&g_dste[base + lane]) : 0;
        int pairs = cnt >> 1;
#pragma unroll 8
        for (int it = 0; it < pairs; it++) {
            int m = __shfl_sync(0xffffffffu, me, 2 * it + half);
            uint4 v = __ldg((const uint4*)(g_h2 + (size_t)m * 128) + l16);
            float2 f0 = __half22float2(*(__half2*)&v.x);
            float2 f1 = __half22float2(*(__half2*)&v.y);
            float2 f2 = __half22float2(*(__half2*)&v.z);
            float2 f3 = __half22float2(*(__half2*)&v.w);
            acc0.x += f0.x; acc0.y += f0.y;
            acc1.x += f1.x; acc1.y += f1.y;
            acc2.x += f2.x; acc2.y += f2.y;
            acc3.x += f3.x; acc3.y += f3.y;
        }
        if (cnt & 1) {
            int m = __shfl_sync(0xffffffffu, me, cnt - 1);
            if (half == 0) {
                uint4 v = __ldg((const uint4*)(g_h2 + (size_t)m * 128) + l16);
                float2 f0 = __half22float2(*(__half2*)&v.x);
                float2 f1 = __half22float2(*(__half2*)&v.y);
                float2 f2 = __half22float2(*(__half2*)&v.z);
                float2 f3 = __half22float2(*(__half2*)&v.w);
                acc0.x += f0.x; acc0.y += f0.y;
                acc1.x += f1.x; acc1.y += f1.y;
                acc2.x += f2.x; acc2.y += f2.y;
                acc3.x += f3.x; acc3.y += f3.y;
            }
        }
    }

    // combine the two edge-parity halves: lane l += lane l+16
    acc0.x += __shfl_down_sync(0xffffffffu, acc0.x, 16);
    acc0.y += __shfl_down_sync(0xffffffffu, acc0.y, 16);
    acc1.x += __shfl_down_sync(0xffffffffu, acc1.x, 16);
    acc1.y += __shfl_down_sync(0xffffffffu, acc1.y, 16);
    acc2.x += __shfl_down_sync(0xffffffffu, acc2.x, 16);
    acc2.y += __shfl_down_sync(0xffffffffu, acc2.y, 16);
    acc3.x += __shfl_down_sync(0xffffffffu, acc3.x, 16);
    acc3.y += __shfl_down_sync(0xffffffffu, acc3.y, 16);

    // per-head weight (finalize folded in: inv = 0.25/sum)
    float4 ev = *reinterpret_cast<const float4*>(&g_expv[gw * 4]);
    int h = l16 >> 2;
    float evh = (h < 2) ? (h == 0 ? ev.x : ev.y) : (h == 2 ? ev.z : ev.w);
    float sh  = (h < 2) ? (h == 0 ? g_sum[0] : g_sum[1]) : (h == 2 ? g_sum[2] : g_sum[3]);
    float aH = evh * (0.25f / sh);
    acc0.x *= aH; acc0.y *= aH;
    acc1.x *= aH; acc1.y *= aH;
    acc2.x *= aH; acc2.y *= aH;
    acc3.x *= aH; acc3.y *= aH;

    // reduce across heads: lanes {q, q+4, q+8, q+12} share f-range
    acc0.x += __shfl_down_sync(0xffffffffu, acc0.x, 8);
    acc0.y += __shfl_down_sync(0xffffffffu, acc0.y, 8);
    acc1.x += __shfl_down_sync(0xffffffffu, acc1.x, 8);
    acc1.y += __shfl_down_sync(0xffffffffu, acc1.y, 8);
    acc2.x += __shfl_down_sync(0xffffffffu, acc2.x, 8);
    acc2.y += __shfl_down_sync(0xffffffffu, acc2.y, 8);
    acc3.x += __shfl_down_sync(0xffffffffu, acc3.x, 8);
    acc3.y += __shfl_down_sync(0xffffffffu, acc3.y, 8);
    acc0.x += __shfl_down_sync(0xffffffffu, acc0.x, 4);
    acc0.y += __shfl_down_sync(0xffffffffu, acc0.y, 4);
    acc1.x += __shfl_down_sync(0xffffffffu, acc1.x, 4);
    acc1.y += __shfl_down_sync(0xffffffffu, acc1.y, 4);
    acc2.x += __shfl_down_sync(0xffffffffu, acc2.x, 4);
    acc2.y += __shfl_down_sync(0xffffffffu, acc2.y, 4);
    acc3.x += __shfl_down_sync(0xffffffffu, acc3.x, 4);
    acc3.y += __shfl_down_sync(0xffffffffu, acc3.y, 4);

    if (lane < 4) {
        float* o = out + (size_t)gw * 32 + 8 * lane;
        *reinterpret_cast<float4*>(o)     = make_float4(acc0.x, acc0.y, acc1.x, acc1.y);
        *reinterpret_cast<float4*>(o + 4) = make_float4(acc2.x, acc2.y, acc3.x, acc3.y);
    }
}

// ---------------------------------------------------------------------------
extern "C" void kernel_launch(void* const* d_in, const int* in_sizes, int n_in,
                              void* d_out, int out_size)
{
    const float* x    = (const float*)d_in[0];
    const int*   ei   = (const int*)d_in[1];
    const float* ea   = (const float*)d_in[2];
    const float* W    = (const float*)d_in[3];
    const float* b    = (const float*)d_in[4];
    const float* eW1  = (const float*)d_in[5];
    const float* eb1  = (const float*)d_in[6];
    const float* eW2  = (const float*)d_in[7];
    const float* eb2  = (const float*)d_in[8];
    const float* asrc = (const float*)d_in[9];
    const float* adst = (const float*)d_in[10];
    float* out = (float*)d_out;

    int N = in_sizes[0] / 128;
    int E = in_sizes[1] / 2;
    const int* srcI = ei;
    const int* dstI = ei + E;
    int nb = (N + 255) / 256;

    cudaFuncSetAttribute(mma_h, cudaFuncAttributeMaxDynamicSharedMemorySize, MMA_SMEM);

    bool fork = (g_side != nullptr) && (g_evF != nullptr) && (g_evJ != nullptr);

    if (fork) {
        // side stream: projection chain (independent of edge chain)
        cudaEventRecord(g_evF, 0);
        cudaStreamWaitEvent(g_side, g_evF, 0);
        prep_w<<<32, 256, 0, g_side>>>(W);
        mma_h<<<(N + 127) / 128, 256, MMA_SMEM, g_side>>>(x, b, asrc, adst, N);
        cudaEventRecord(g_evJ, g_side);
    } else {
        prep_w<<<32, 256>>>(W);
        mma_h<<<(N + 127) / 128, 256, MMA_SMEM>>>(x, b, asrc, adst, N);
    }

    // main stream: edge chain
    init_k<<<(N + 255) / 256, 256>>>(N);
    last_cnt_k<<<((E + 3) / 4 + 255) / 256, 256>>>(srcI, E);
    scan1<<<nb, 256>>>(N);
    scan2<<<1, 256>>>(nb, N, E);
    scan3<<<nb, 256>>>(N);
    reorder_k<<<((E + 3) / 4 + 255) / 256, 256>>>(srcI, dstI, E);

    if (fork) cudaStreamWaitEvent(0, g_evJ, 0);   // join: alpha needs g_s/g_d + g_last

    alpha_k<<<(N * 8 + 255) / 256, 256>>>(dstI, ea, eW1, eb1, eW2, eb2, N);
    segsum_k<<<(N * 32 + 255) / 256, 256>>>(out, N);
}

// round 7
// speedup vs baseline: 2.6649x; 1.6461x over previous
#include <cuda_runtime.h>
#include <cuda_fp16.h>
#include <cstdint>

#define NN 50000
#define NE 1600000

// ---------------- device scratch (no allocation allowed) -------------------
__device__ __half g_h2[NN * 128];      // fp16 projected features
__device__ float  g_s[NN * 4];         // alpha_src per node/head
__device__ float  g_d[NN * 4];         // alpha_dst per node/head
__device__ int    g_cnt[NN];           // out-degree histogram
__device__ int    g_start[NN + 1];     // segment starts
__device__ int    g_pos[NN];           // placement cursors
__device__ int2   g_edge[NE];          // (dst, eid) sorted by src
__device__ float  g_expv[NN * 4];      // exp(leaky(logit)) per valid node/head
__device__ float  g_sum[256];          // denominators at h*64 (256B apart -> distinct LTS)
__device__ __align__(16) unsigned char g_Bsw[128 * 128 * 2];  // W^T fp16, swizzled
__device__ int    g_bsum[256];         // scan block sums

__device__ __forceinline__ uint32_t smem_u32(const void* p) {
    uint32_t a;
    asm("{ .reg .u64 t; cvta.to.shared.u64 t, %1; cvt.u32.u64 %0, t; }" : "=r"(a) : "l"(p));
    return a;
}

// ---------------- streams/events for fork-join (created pre-main) ----------
static cudaStream_t g_side = nullptr;
static cudaEvent_t  g_evF  = nullptr;
static cudaEvent_t  g_evJ  = nullptr;
namespace {
struct CudaInit {
    CudaInit() {
        cudaStreamCreateWithFlags(&g_side, cudaStreamNonBlocking);
        cudaEventCreateWithFlags(&g_evF, cudaEventDisableTiming);
        cudaEventCreateWithFlags(&g_evJ, cudaEventDisableTiming);
    }
} g_cudainit;
}

// ---------------------------------------------------------------------------
// P0: W -> g_Bsw: B[n][k] = W[k][n] fp16, rows of 256B, 16B-chunk XOR swizzle.
// ---------------------------------------------------------------------------
__global__ void prep_w(const float* __restrict__ W)
{
    int idx = blockIdx.x * 256 + threadIdx.x;
    if (idx >= 128 * 64) return;
    int n = idx >> 6;
    int k = (idx & 63) * 2;
    __half2 p = __floats2half2_rn(__ldg(&W[k * 128 + n]), __ldg(&W[(k + 1) * 128 + n]));
    uint32_t off = (uint32_t)n * 256u
                 + (uint32_t)(((k >> 3) ^ (n & 7)) << 4)
                 + (uint32_t)(k & 7) * 2u;
    *(uint32_t*)(g_Bsw + off) = *(uint32_t*)&p;
}

// ---------------------------------------------------------------------------
// K1: h = x@W + b via mma.sync m16n8k16 (fp16 in, fp32 acc). Epilogue fused.
// ---------------------------------------------------------------------------
#define MMA_SMEM 65536

__global__ __launch_bounds__(256, 2)
void mma_h(const float* __restrict__ x, const float* __restrict__ b,
           const float* __restrict__ asrc, const float* __restrict__ adst, int N)
{
    extern __shared__ char smem[];
    const int tid  = threadIdx.x;
    const int wid  = tid >> 5;
    const int lane = tid & 31;
    const int row0 = blockIdx.x * 128;

    {
        const uint4* s4 = (const uint4*)g_Bsw;
        uint4* d4 = (uint4*)(smem + 32768);
#pragma unroll
        for (int i = 0; i < 8; i++) d4[tid + 256 * i] = s4[tid + 256 * i];
    }
    {
        int r  = tid >> 1;
        int c0 = (tid & 1) * 64;
        int rr = row0 + r; if (rr >= N) rr = N - 1;
        const float4* xr = (const float4*)(x + (size_t)rr * 128 + c0);
        char* rowbase = smem + r * 256;
#pragma unroll
        for (int q = 0; q < 16; q++) {
            float4 v = __ldg(&xr[q]);
            int c = c0 + q * 4;
            __half2 h0 = __floats2half2_rn(v.x, v.y);
            __half2 h1 = __floats2half2_rn(v.z, v.w);
            uint2 pk;
            pk.x = *(uint32_t*)&h0;
            pk.y = *(uint32_t*)&h1;
            int off = (((c >> 3) ^ (r & 7)) << 4) + (c & 7) * 2;
            *(uint2*)(rowbase + off) = pk;
        }
    }
    __syncthreads();

    const uint32_t smA = smem_u32(smem);
    const uint32_t smB = smA + 32768;

    float acc[16][4];
#pragma unroll
    for (int nt = 0; nt < 16; nt++)
#pragma unroll
        for (int j = 0; j < 4; j++) acc[nt][j] = 0.f;

    const int sub  = lane & 7;
    const int amat = lane >> 3;
    const int arow = wid * 16 + sub + (amat & 1) * 8;
    const int achk = amat >> 1;
    const int bchk = (lane >> 3) & 1;

#pragma unroll
    for (int k = 0; k < 8; k++) {
        uint32_t a0, a1, a2, a3;
        {
            uint32_t addr = smA + arow * 256 + ((((k * 2 + achk)) ^ (arow & 7)) << 4);
            asm volatile("ldmatrix.sync.aligned.m8n8.x4.shared.b16 {%0,%1,%2,%3}, [%4];"
                         : "=r"(a0), "=r"(a1), "=r"(a2), "=r"(a3) : "r"(addr));
        }
#pragma unroll
        for (int nt = 0; nt < 16; nt++) {
            int brow = nt * 8 + sub;
            uint32_t baddr = smB + brow * 256 + ((((k * 2 + bchk)) ^ (brow & 7)) << 4);
            uint32_t b0, b1;
            asm volatile("ldmatrix.sync.aligned.m8n8.x2.shared.b16 {%0,%1}, [%2];"
                         : "=r"(b0), "=r"(b1) : "r"(baddr));
            asm volatile(
                "mma.sync.aligned.m16n8k16.row.col.f32.f16.f16.f32 "
                "{%0,%1,%2,%3}, {%4,%5,%6,%7}, {%8,%9}, {%0,%1,%2,%3};"
                : "+f"(acc[nt][0]), "+f"(acc[nt][1]), "+f"(acc[nt][2]), "+f"(acc[nt][3])
                : "r"(a0), "r"(a1), "r"(a2), "r"(a3), "r"(b0), "r"(b1));
        }
    }

    const int gID = lane >> 2;
    const int tIG = lane & 3;
    const int r0  = row0 + wid * 16 + gID;
    const int r1  = r0 + 8;

    float ps0[4], pd0[4], ps1[4], pd1[4];
#pragma unroll
    for (int h = 0; h < 4; h++) { ps0[h] = pd0[h] = ps1[h] = pd1[h] = 0.f; }
    uint32_t pk0[16], pk1[16];

#pragma unroll
    for (int nt = 0; nt < 16; nt++) {
        int c0 = nt * 8 + tIG * 2;
        float bb0 = __ldg(&b[c0]),    bb1 = __ldg(&b[c0 + 1]);
        float as0 = __ldg(&asrc[c0]), as1 = __ldg(&asrc[c0 + 1]);
        float ad0 = __ldg(&adst[c0]), ad1 = __ldg(&adst[c0 + 1]);
        float v00 = acc[nt][0] + bb0, v01 = acc[nt][1] + bb1;
        float v10 = acc[nt][2] + bb0, v11 = acc[nt][3] + bb1;
        int h = nt >> 2;
        ps0[h] += v00 * as0 + v01 * as1;
        pd0[h] += v00 * ad0 + v01 * ad1;
        ps1[h] += v10 * as0 + v11 * as1;
        pd1[h] += v10 * ad0 + v11 * ad1;
        __half2 q0 = __floats2half2_rn(v00, v01);
        __half2 q1 = __floats2half2_rn(v10, v11);
        pk0[nt] = *(uint32_t*)&q0;
        pk1[nt] = *(uint32_t*)&q1;
    }
#pragma unroll
    for (int h = 0; h < 4; h++) {
        ps0[h] += __shfl_down_sync(0xffffffffu, ps0[h], 2, 4);
        ps0[h] += __shfl_down_sync(0xffffffffu, ps0[h], 1, 4);
        pd0[h] += __shfl_down_sync(0xffffffffu, pd0[h], 2, 4);
        pd0[h] += __shfl_down_sync(0xffffffffu, pd0[h], 1, 4);
        ps1[h] += __shfl_down_sync(0xffffffffu, ps1[h], 2, 4);
        ps1[h] += __shfl_down_sync(0xffffffffu, ps1[h], 1, 4);
        pd1[h] += __shfl_down_sync(0xffffffffu, pd1[h], 2, 4);
        pd1[h] += __shfl_down_sync(0xffffffffu, pd1[h], 1, 4);
    }
    if (r0 < N) {
#pragma unroll
        for (int nt = 0; nt < 16; nt++)
            *(uint32_t*)&g_h2[(size_t)r0 * 128 + nt * 8 + tIG * 2] = pk0[nt];
        if (tIG == 0) {
#pragma unroll
            for (int h = 0; h < 4; h++) {
                g_s[r0 * 4 + h] = ps0[h];
                g_d[r0 * 4 + h] = pd0[h];
            }
        }
    }
    if (r1 < N) {
#pragma unroll
        for (int nt = 0; nt < 16; nt++)
            *(uint32_t*)&g_h2[(size_t)r1 * 128 + nt * 8 + tIG * 2] = pk1[nt];
        if (tIG == 0) {
#pragma unroll
            for (int h = 0; h < 4; h++) {
                g_s[r1 * 4 + h] = ps1[h];
                g_d[r1 * 4 + h] = pd1[h];
            }
        }
    }
}

// ---------------------------------------------------------------------------
__global__ void init_k(int N)
{
    int i = blockIdx.x * blockDim.x + threadIdx.x;
    if (i < N) g_cnt[i] = 0;
    if (i < 256) g_sum[i] = 0.f;
}

// K3: degree histogram only (atomicMax eliminated).
__global__ void cnt_k(const int* __restrict__ src, int E)
{
    int i = blockIdx.x * blockDim.x + threadIdx.x;
    int e0 = i * 4;
    if (e0 + 3 < E) {
        int4 s = *reinterpret_cast<const int4*>(&src[e0]);
        atomicAdd(&g_cnt[s.x], 1);
        atomicAdd(&g_cnt[s.y], 1);
        atomicAdd(&g_cnt[s.z], 1);
        atomicAdd(&g_cnt[s.w], 1);
    } else {
        for (int e = e0; e < E; e++) atomicAdd(&g_cnt[src[e]], 1);
    }
}

// ---------------------------------------------------------------------------
// Scan, 3 phases.
// ---------------------------------------------------------------------------
__device__ __forceinline__ int block_incl_scan(int v, int t)
{
    __shared__ int ws[8];
    int lane = t & 31, w = t >> 5;
    int xv = v;
#pragma unroll
    for (int o = 1; o < 32; o <<= 1) {
        int u = __shfl_up_sync(0xffffffffu, xv, o);
        if (lane >= o) xv += u;
    }
    if (lane == 31) ws[w] = xv;
    __syncthreads();
    if (t < 8) {
        int y = ws[t];
#pragma unroll
        for (int o = 1; o < 8; o <<= 1) {
            int u = __shfl_up_sync(0xffu, y, o);
            if (t >= o) y += u;
        }
        ws[t] = y;
    }
    __syncthreads();
    return xv + (w > 0 ? ws[w - 1] : 0);
}

__global__ __launch_bounds__(256) void scan1(int N)
{
    int i = blockIdx.x * 256 + threadIdx.x;
    int v = (i < N) ? g_cnt[i] : 0;
    int incl = block_incl_scan(v, threadIdx.x);
    if (threadIdx.x == 255) g_bsum[blockIdx.x] = incl;
}

__global__ __launch_bounds__(256) void scan2(int nb, int N, int E)
{
    int t = threadIdx.x;
    int v = (t < nb) ? g_bsum[t] : 0;
    int incl = block_incl_scan(v, t);
    if (t < nb) g_bsum[t] = incl - v;
    if (t == 0) g_start[N] = E;
}

__global__ __launch_bounds__(256) void scan3(int N)
{
    int i = blockIdx.x * 256 + threadIdx.x;
    int v = (i < N) ? g_cnt[i] : 0;
    int incl = block_incl_scan(v, threadIdx.x);
    if (i < N) {
        int e = incl - v + g_bsum[blockIdx.x];
        g_start[i] = e;
        g_pos[i]   = e;
    }
}

// ---------------------------------------------------------------------------
// K5: reorder: place (dst, eid) into src segment. int2 store = same sectors.
// ---------------------------------------------------------------------------
__global__ void reorder_k(const int* __restrict__ src,
                          const int* __restrict__ dstI, int E)
{
    int i = blockIdx.x * blockDim.x + threadIdx.x;
    int e0 = i * 4;
    if (e0 + 3 < E) {
        int4 s = *reinterpret_cast<const int4*>(&src[e0]);
        int4 d = *reinterpret_cast<const int4*>(&dstI[e0]);
        g_edge[atomicAdd(&g_pos[s.x], 1)] = make_int2(d.x, e0);
        g_edge[atomicAdd(&g_pos[s.y], 1)] = make_int2(d.y, e0 + 1);
        g_edge[atomicAdd(&g_pos[s.z], 1)] = make_int2(d.z, e0 + 2);
        g_edge[atomicAdd(&g_pos[s.w], 1)] = make_int2(d.w, e0 + 3);
    } else {
        for (int e = e0; e < E; e++)
            g_edge[atomicAdd(&g_pos[src[e]], 1)] = make_int2(dstI[e], e);
    }
}

// ---------------------------------------------------------------------------
// K6: alpha, one warp per node. Segment-scan argmax(eid) replaces g_last.
// Lane = hidden unit (EDGE_HID=32). Block-reduced, LTS-padded denominators.
// ---------------------------------------------------------------------------
__global__ __launch_bounds__(256) void alpha_k(const float* __restrict__ eattr,
                                               const float* __restrict__ eW1,
                                               const float* __restrict__ eb1,
                                               const float* __restrict__ eW2,
                                               const float* __restrict__ eb2,
                                               int N)
{
    __shared__ float sred[8][4];
    const int wIB  = threadIdx.x >> 5;
    const int lane = threadIdx.x & 31;
    const int gw   = blockIdx.x * 8 + wIB;

    float ev0 = 0.f, ev1 = 0.f, ev2 = 0.f, ev3 = 0.f;

    if (gw < N) {
        int s0 = g_start[gw];
        int s1 = g_start[gw + 1];
        if (s1 > s0) {
            // segment argmax by eid
            int be = -1, bd = 0;
            for (int base = s0; base < s1; base += 32) {
                int idx = base + lane;
                int2 v = (idx < s1) ? __ldg(&g_edge[idx]) : make_int2(0, -1);
                if (v.y > be) { be = v.y; bd = v.x; }
            }
#pragma unroll
            for (int off = 16; off > 0; off >>= 1) {
                int oe = __shfl_down_sync(0xffffffffu, be, off);
                int od = __shfl_down_sync(0xffffffffu, bd, off);
                if (oe > be) { be = oe; bd = od; }
            }
            be = __shfl_sync(0xffffffffu, be, 0);
            bd = __shfl_sync(0xffffffffu, bd, 0);

            // edge MLP: lane = hidden unit j
            float4 ea = __ldg((const float4*)(eattr + (size_t)be * 4));
            float hid = fmaf(ea.x, __ldg(&eW1[lane]),
                        fmaf(ea.y, __ldg(&eW1[32 + lane]),
                        fmaf(ea.z, __ldg(&eW1[64 + lane]),
                        fmaf(ea.w, __ldg(&eW1[96 + lane]), __ldg(&eb1[lane])))));
            hid = fmaxf(hid, 0.f);
            float4 w2 = __ldg((const float4*)(eW2 + lane * 4));
            float vh0 = hid * w2.x, vh1 = hid * w2.y, vh2 = hid * w2.z, vh3 = hid * w2.w;
#pragma unroll
            for (int off = 16; off > 0; off >>= 1) {
                vh0 += __shfl_down_sync(0xffffffffu, vh0, off);
                vh1 += __shfl_down_sync(0xffffffffu, vh1, off);
                vh2 += __shfl_down_sync(0xffffffffu, vh2, off);
                vh3 += __shfl_down_sync(0xffffffffu, vh3, off);
            }
            if (lane == 0) {
                float v0 = g_s[gw * 4 + 0] + g_d[bd * 4 + 0] + vh0 + __ldg(&eb2[0]);
                float v1 = g_s[gw * 4 + 1] + g_d[bd * 4 + 1] + vh1 + __ldg(&eb2[1]);
                float v2 = g_s[gw * 4 + 2] + g_d[bd * 4 + 2] + vh2 + __ldg(&eb2[2]);
                float v3 = g_s[gw * 4 + 3] + g_d[bd * 4 + 3] + vh3 + __ldg(&eb2[3]);
                v0 = v0 > 0.f ? v0 : 0.2f * v0;
                v1 = v1 > 0.f ? v1 : 0.2f * v1;
                v2 = v2 > 0.f ? v2 : 0.2f * v2;
                v3 = v3 > 0.f ? v3 : 0.2f * v3;
                ev0 = expf(v0); ev1 = expf(v1); ev2 = expf(v2); ev3 = expf(v3);
                *reinterpret_cast<float4*>(&g_expv[gw * 4]) = make_float4(ev0, ev1, ev2, ev3);
            }
        }
    }
    if (lane == 0) {
        sred[wIB][0] = ev0; sred[wIB][1] = ev1; sred[wIB][2] = ev2; sred[wIB][3] = ev3;
    }
    __syncthreads();
    if (threadIdx.x < 4) {
        float s = 0.f;
#pragma unroll
        for (int w = 0; w < 8; w++) s += sred[w][threadIdx.x];
        atomicAdd(&g_sum[threadIdx.x * 64], s);   // 256B apart -> distinct LTS
    }
}

// ---------------------------------------------------------------------------
// K7: segment-sum, one warp/node, 2 edges/iter, uint4 gathers, no atomics.
// ---------------------------------------------------------------------------
__global__ __launch_bounds__(256) void segsum_k(float* __restrict__ out, int N)
{
    int gw   = (blockIdx.x * 256 + threadIdx.x) >> 5;
    int lane = threadIdx.x & 31;
    if (gw >= N) return;

    const int s0 = g_start[gw];
    const int s1 = g_start[gw + 1];
    const int half = lane >> 4;
    const int l16  = lane & 15;

    float2 acc0 = make_float2(0.f, 0.f), acc1 = make_float2(0.f, 0.f);
    float2 acc2 = make_float2(0.f, 0.f), acc3 = make_float2(0.f, 0.f);

    for (int base = s0; base < s1; base += 32) {
        int cnt = s1 - base; if (cnt > 32) cnt = 32;
        int me = (lane < cnt) ? __ldg(&g_edge[base + lane]).x : 0;
        int pairs = cnt >> 1;
#pragma unroll 8
        for (int it = 0; it < pairs; it++) {
            int m = __shfl_sync(0xffffffffu, me, 2 * it + half);
            uint4 v = __ldg((const uint4*)(g_h2 + (size_t)m * 128) + l16);
            float2 f0 = __half22float2(*(__half2*)&v.x);
            float2 f1 = __half22float2(*(__half2*)&v.y);
            float2 f2 = __half22float2(*(__half2*)&v.z);
            float2 f3 = __half22float2(*(__half2*)&v.w);
            acc0.x += f0.x; acc0.y += f0.y;
            acc1.x += f1.x; acc1.y += f1.y;
            acc2.x += f2.x; acc2.y += f2.y;
            acc3.x += f3.x; acc3.y += f3.y;
        }
        if (cnt & 1) {
            int m = __shfl_sync(0xffffffffu, me, cnt - 1);
            if (half == 0) {
                uint4 v = __ldg((const uint4*)(g_h2 + (size_t)m * 128) + l16);
                float2 f0 = __half22float2(*(__half2*)&v.x);
                float2 f1 = __half22float2(*(__half2*)&v.y);
                float2 f2 = __half22float2(*(__half2*)&v.z);
                float2 f3 = __half22float2(*(__half2*)&v.w);
                acc0.x += f0.x; acc0.y += f0.y;
                acc1.x += f1.x; acc1.y += f1.y;
                acc2.x += f2.x; acc2.y += f2.y;
                acc3.x += f3.x; acc3.y += f3.y;
            }
        }
    }

    acc0.x += __shfl_down_sync(0xffffffffu, acc0.x, 16);
    acc0.y += __shfl_down_sync(0xffffffffu, acc0.y, 16);
    acc1.x += __shfl_down_sync(0xffffffffu, acc1.x, 16);
    acc1.y += __shfl_down_sync(0xffffffffu, acc1.y, 16);
    acc2.x += __shfl_down_sync(0xffffffffu, acc2.x, 16);
    acc2.y += __shfl_down_sync(0xffffffffu, acc2.y, 16);
    acc3.x += __shfl_down_sync(0xffffffffu, acc3.x, 16);
    acc3.y += __shfl_down_sync(0xffffffffu, acc3.y, 16);

    float4 ev = *reinterpret_cast<const float4*>(&g_expv[gw * 4]);
    int h = l16 >> 2;
    float evh = (h < 2) ? (h == 0 ? ev.x : ev.y) : (h == 2 ? ev.z : ev.w);
    float sh  = g_sum[h * 64];
    float aH = evh * (0.25f / sh);
    acc0.x *= aH; acc0.y *= aH;
    acc1.x *= aH; acc1.y *= aH;
    acc2.x *= aH; acc2.y *= aH;
    acc3.x *= aH; acc3.y *= aH;

    acc0.x += __shfl_down_sync(0xffffffffu, acc0.x, 8);
    acc0.y += __shfl_down_sync(0xffffffffu, acc0.y, 8);
    acc1.x += __shfl_down_sync(0xffffffffu, acc1.x, 8);
    acc1.y += __shfl_down_sync(0xffffffffu, acc1.y, 8);
    acc2.x += __shfl_down_sync(0xffffffffu, acc2.x, 8);
    acc2.y += __shfl_down_sync(0xffffffffu, acc2.y, 8);
    acc3.x += __shfl_down_sync(0xffffffffu, acc3.x, 8);
    acc3.y += __shfl_down_sync(0xffffffffu, acc3.y, 8);
    acc0.x += __shfl_down_sync(0xffffffffu, acc0.x, 4);
    acc0.y += __shfl_down_sync(0xffffffffu, acc0.y, 4);
    acc1.x += __shfl_down_sync(0xffffffffu, acc1.x, 4);
    acc1.y += __shfl_down_sync(0xffffffffu, acc1.y, 4);
    acc2.x += __shfl_down_sync(0xffffffffu, acc2.x, 4);
    acc2.y += __shfl_down_sync(0xffffffffu, acc2.y, 4);
    acc3.x += __shfl_down_sync(0xffffffffu, acc3.x, 4);
    acc3.y += __shfl_down_sync(0xffffffffu, acc3.y, 4);

    if (lane < 4) {
        float* o = out + (size_t)gw * 32 + 8 * lane;
        *reinterpret_cast<float4*>(o)     = make_float4(acc0.x, acc0.y, acc1.x, acc1.y);
        *reinterpret_cast<float4*>(o + 4) = make_float4(acc2.x, acc2.y, acc3.x, acc3.y);
    }
}

// ---------------------------------------------------------------------------
extern "C" void kernel_launch(void* const* d_in, const int* in_sizes, int n_in,
                              void* d_out, int out_size)
{
    const float* x    = (const float*)d_in[0];
    const int*   ei   = (const int*)d_in[1];
    const float* ea   = (const float*)d_in[2];
    const float* W    = (const float*)d_in[3];
    const float* b    = (const float*)d_in[4];
    const float* eW1  = (const float*)d_in[5];
    const float* eb1  = (const float*)d_in[6];
    const float* eW2  = (const float*)d_in[7];
    const float* eb2  = (const float*)d_in[8];
    const float* asrc = (const float*)d_in[9];
    const float* adst = (const float*)d_in[10];
    float* out = (float*)d_out;

    int N = in_sizes[0] / 128;
    int E = in_sizes[1] / 2;
    const int* srcI = ei;
    const int* dstI = ei + E;
    int nb = (N + 255) / 256;

    cudaFuncSetAttribute(mma_h, cudaFuncAttributeMaxDynamicSharedMemorySize, MMA_SMEM);

    bool fork = (g_side != nullptr) && (g_evF != nullptr) && (g_evJ != nullptr);

    if (fork) {
        cudaEventRecord(g_evF, 0);
        cudaStreamWaitEvent(g_side, g_evF, 0);
        prep_w<<<32, 256, 0, g_side>>>(W);
        mma_h<<<(N + 127) / 128, 256, MMA_SMEM, g_side>>>(x, b, asrc, adst, N);
        cudaEventRecord(g_evJ, g_side);
    } else {
        prep_w<<<32, 256>>>(W);
        mma_h<<<(N + 127) / 128, 256, MMA_SMEM>>>(x, b, asrc, adst, N);
    }

    init_k<<<(N + 255) / 256, 256>>>(N);
    cnt_k<<<((E + 3) / 4 + 255) / 256, 256>>>(srcI, E);
    scan1<<<nb, 256>>>(N);
    scan2<<<1, 256>>>(nb, N, E);
    scan3<<<nb, 256>>>(N);
    reorder_k<<<((E + 3) / 4 + 255) / 256, 256>>>(srcI, dstI, E);

    if (fork) cudaStreamWaitEvent(0, g_evJ, 0);

    alpha_k<<<(N + 7) / 8, 256>>>(ea, eW1, eb1, eW2, eb2, N);
    segsum_k<<<(N * 32 + 255) / 256, 256>>>(out, N);
}